// round 12
// baseline (speedup 1.0000x reference)
#include <cuda_runtime.h>
#include <cuda_bf16.h>
#include <cuda_fp16.h>
#include <stdint.h>
#include <math.h>

#define NN 50000
#define NN2 (2 * NN)
#define NE 800000
#define ET2 (2 * (NN + NE))
#define NB 512
#define ND 256
#define NH 4
#define HC 64

// ---------------- static device scratch ----------------
__device__ float g_x[(size_t)NN2 * ND];
__device__ __nv_bfloat16 g_xhi[(size_t)NN2 * ND];
__device__ __nv_bfloat16 g_xlo[(size_t)NN2 * ND];
__device__ __nv_bfloat16 g_whi[3 * ND * ND];   // transposed [l][n][k]
__device__ __nv_bfloat16 g_wlo[3 * ND * ND];
__device__ __half g_hf[(size_t)NN2 * ND];      // h in fp16 (gather plane)
__device__ float g_asrc[NN2 * NH];
__device__ float g_adst[NN2 * NH];
__device__ int   g_counts[NN2];
__device__ int   g_off[NN2];
__device__ int   g_cur[NN2];
__device__ int   g_srcs[ET2];
__device__ int   g_total;
__device__ float g_he[NB * ND];
__device__ float g_te[NB * ND];

// ---------------- fp32 -> bf16 hi/lo split ----------------
__device__ __forceinline__ void split_bf16(float v, __nv_bfloat16& hi, __nv_bfloat16& lo) {
    hi = __float2bfloat16(v);
    lo = __float2bfloat16(v - __bfloat162float(hi));
}

__global__ void k_split_x(const float* __restrict__ xh, const float* __restrict__ xt) {
    const int n4 = NN2 * ND / 4;
    const int h4 = NN * ND / 4;
    int i = blockIdx.x * blockDim.x + threadIdx.x;
    int stride = gridDim.x * blockDim.x;
    for (; i < n4; i += stride) {
        float4 v = (i < h4) ? ((const float4*)xh)[i] : ((const float4*)xt)[i - h4];
        __nv_bfloat16 h0, l0, h1, l1, h2, l2, h3, l3;
        split_bf16(v.x, h0, l0);
        split_bf16(v.y, h1, l1);
        split_bf16(v.z, h2, l2);
        split_bf16(v.w, h3, l3);
        __nv_bfloat162 hv0(h0, h1), hv1(h2, h3), lv0(l0, l1), lv1(l2, l3);
        uint2 hp, lp;
        hp.x = *(unsigned*)&hv0; hp.y = *(unsigned*)&hv1;
        lp.x = *(unsigned*)&lv0; lp.y = *(unsigned*)&lv1;
        ((uint2*)g_xhi)[i] = hp;
        ((uint2*)g_xlo)[i] = lp;
    }
}

__global__ void k_split_w(const float* __restrict__ Ws) {
    int i = blockIdx.x * blockDim.x + threadIdx.x;
    if (i >= 3 * ND * ND) return;
    int l = i / (ND * ND);
    int r = i % (ND * ND);
    int n = r / ND;
    int k = r % ND;
    float v = Ws[l * ND * ND + k * ND + n];
    __nv_bfloat16 hi, lo;
    split_bf16(v, hi, lo);
    g_whi[i] = hi;
    g_wlo[i] = lo;
}

// ---------------- merged CSR construction ----------------
__global__ void k_init_counts() {
    int i = blockIdx.x * blockDim.x + threadIdx.x;
    if (i < NN2) g_counts[i] = 1;   // self-loop pre-counted
    if (i == 0) g_total = 0;
}

__global__ void k_count(const int* __restrict__ eh, const int* __restrict__ et) {
    int e = blockIdx.x * blockDim.x + threadIdx.x;
    if (e >= 2 * NE) return;
    int d = (e < NE) ? eh[NE + e] : (et[NE + (e - NE)] + NN);
    atomicAdd(&g_counts[d], 1);
}

__global__ void k_assign() {
    int i = blockIdx.x * blockDim.x + threadIdx.x;
    int lane = threadIdx.x & 31;
    int v = (i < NN2) ? g_counts[i] : 0;
    int inc = v;
#pragma unroll
    for (int o = 1; o < 32; o <<= 1) {
        int t = __shfl_up_sync(0xffffffffu, inc, o);
        if (lane >= o) inc += t;
    }
    int wtot = __shfl_sync(0xffffffffu, inc, 31);
    int base = 0;
    if (lane == 31) base = atomicAdd(&g_total, wtot);
    base = __shfl_sync(0xffffffffu, base, 31);
    if (i < NN2) {
        int p = base + inc - v;
        g_off[i] = p;
        g_cur[i] = p;
    }
}

__global__ void k_scatter(const int* __restrict__ eh, const int* __restrict__ et) {
    int e = blockIdx.x * blockDim.x + threadIdx.x;
    if (e >= 2 * NE) return;
    int s, d;
    if (e < NE) {
        s = eh[e];
        d = eh[NE + e];
    } else {
        s = et[e - NE] + NN;
        d = et[NE + (e - NE)] + NN;
    }
    int p = atomicAdd(&g_cur[d], 1);
    g_srcs[p] = s;
}

__global__ void k_selfloops() {
    int i = blockIdx.x * blockDim.x + threadIdx.x;
    if (i >= NN2) return;
    int p = atomicAdd(&g_cur[i], 1);
    g_srcs[p] = i;
}

// ---------------- bf16x3 tensor-core GEMM + fused att-score epilogue ----------------
__device__ __forceinline__ void mma16816(float* c, const unsigned* a, const unsigned* b) {
    asm volatile(
        "mma.sync.aligned.m16n8k16.row.col.f32.bf16.bf16.f32 "
        "{%0,%1,%2,%3},{%4,%5,%6,%7},{%8,%9},{%0,%1,%2,%3};"
        : "+f"(c[0]), "+f"(c[1]), "+f"(c[2]), "+f"(c[3])
        : "r"(a[0]), "r"(a[1]), "r"(a[2]), "r"(a[3]), "r"(b[0]), "r"(b[1]));
}

#define LDP 40
#define ARR_B 10240
#define BUF_B 40960
#define GSMEM (2 * BUF_B)

__device__ __forceinline__ void cp16(uint32_t dst, const void* src, bool pred) {
    asm volatile("cp.async.cg.shared.global [%0], [%1], 16, %2;"
                 :: "r"(dst), "l"(src), "r"(pred ? 16 : 0));
}

__global__ void __launch_bounds__(256, 2) k_gemm(const __nv_bfloat16* __restrict__ whi,
                                                 const __nv_bfloat16* __restrict__ wlo,
                                                 const float* __restrict__ a_s,
                                                 const float* __restrict__ a_d) {
    extern __shared__ __align__(16) unsigned char smem[];
    uint32_t smem_s = (uint32_t)__cvta_generic_to_shared(smem);
    int tid = threadIdx.x;
    int bx = blockIdx.x;
    int mBase = blockIdx.y * 128, nBase = bx * 128;
    int w = tid >> 5, lane = tid & 31;
    int wm = w >> 2, wn = w & 3;
    int g = lane >> 2, thr = lane & 3;
    float c[4][4][4];
#pragma unroll
    for (int a = 0; a < 4; a++)
#pragma unroll
        for (int b = 0; b < 4; b++)
#pragma unroll
            for (int d = 0; d < 4; d++) c[a][b][d] = 0.f;

    int i0 = tid, i1 = tid + 256;
    int r0c = i0 >> 2, ch0 = (i0 & 3) * 8;
    int r1c = i1 >> 2, ch1 = (i1 & 3) * 8;
    bool p0 = (mBase + r0c) < NN2, p1 = (mBase + r1c) < NN2;
    size_t aof0 = (size_t)(mBase + r0c) * ND + ch0;
    size_t aof1 = (size_t)(mBase + r1c) * ND + ch1;
    size_t bof0 = (size_t)(nBase + r0c) * ND + ch0;
    size_t bof1 = (size_t)(nBase + r1c) * ND + ch1;
    uint32_t d00 = smem_s + r0c * 80 + ch0 * 2;
    uint32_t d01 = smem_s + r1c * 80 + ch1 * 2;

    auto issue = [&](int t, int buf) {
        int k0 = t * 32;
        uint32_t bb = (uint32_t)buf * BUF_B;
        cp16(d00 + bb,             g_xhi + aof0 + k0, p0);
        cp16(d01 + bb,             g_xhi + aof1 + k0, p1);
        cp16(d00 + bb + ARR_B,     g_xlo + aof0 + k0, p0);
        cp16(d01 + bb + ARR_B,     g_xlo + aof1 + k0, p1);
        cp16(d00 + bb + 2 * ARR_B, whi + bof0 + k0, true);
        cp16(d01 + bb + 2 * ARR_B, whi + bof1 + k0, true);
        cp16(d00 + bb + 3 * ARR_B, wlo + bof0 + k0, true);
        cp16(d01 + bb + 3 * ARR_B, wlo + bof1 + k0, true);
        asm volatile("cp.async.commit_group;");
    };

    issue(0, 0);
    for (int t = 0; t < 8; t++) {
        if (t < 7) {
            issue(t + 1, (t + 1) & 1);
            asm volatile("cp.async.wait_group 1;");
        } else {
            asm volatile("cp.async.wait_group 0;");
        }
        __syncthreads();

        const __nv_bfloat16* Ah = (const __nv_bfloat16*)(smem + (t & 1) * BUF_B);
        const __nv_bfloat16* Al = Ah + 5120;
        const __nv_bfloat16* Bh = Ah + 10240;
        const __nv_bfloat16* Bl = Ah + 15360;

#pragma unroll
        for (int kk = 0; kk < 32; kk += 16) {
            unsigned bhf[4][2], blf[4][2];
#pragma unroll
            for (int ni = 0; ni < 4; ni++) {
                int nr = wn * 32 + ni * 8 + g;
                bhf[ni][0] = *(const unsigned*)&Bh[nr * LDP + kk + thr * 2];
                bhf[ni][1] = *(const unsigned*)&Bh[nr * LDP + kk + thr * 2 + 8];
                blf[ni][0] = *(const unsigned*)&Bl[nr * LDP + kk + thr * 2];
                blf[ni][1] = *(const unsigned*)&Bl[nr * LDP + kk + thr * 2 + 8];
            }
#pragma unroll
            for (int mi = 0; mi < 4; mi++) {
                int r0 = wm * 64 + mi * 16 + g;
                unsigned ahf[4], alf[4];
                ahf[0] = *(const unsigned*)&Ah[r0 * LDP + kk + thr * 2];
                ahf[1] = *(const unsigned*)&Ah[(r0 + 8) * LDP + kk + thr * 2];
                ahf[2] = *(const unsigned*)&Ah[r0 * LDP + kk + thr * 2 + 8];
                ahf[3] = *(const unsigned*)&Ah[(r0 + 8) * LDP + kk + thr * 2 + 8];
                alf[0] = *(const unsigned*)&Al[r0 * LDP + kk + thr * 2];
                alf[1] = *(const unsigned*)&Al[(r0 + 8) * LDP + kk + thr * 2];
                alf[2] = *(const unsigned*)&Al[r0 * LDP + kk + thr * 2 + 8];
                alf[3] = *(const unsigned*)&Al[(r0 + 8) * LDP + kk + thr * 2 + 8];
#pragma unroll
                for (int ni = 0; ni < 4; ni++) {
                    mma16816(c[mi][ni], ahf, bhf[ni]);
                    mma16816(c[mi][ni], ahf, blf[ni]);
                    mma16816(c[mi][ni], alf, bhf[ni]);
                }
            }
        }
        __syncthreads();
    }

    // ---- store h (fp16 gather plane) ----
#pragma unroll
    for (int mi = 0; mi < 4; mi++) {
        int row0 = mBase + wm * 64 + mi * 16 + g;
#pragma unroll
        for (int ni = 0; ni < 4; ni++) {
            int col = nBase + wn * 32 + ni * 8 + thr * 2;
            if (row0 < NN2)
                *(__half2*)&g_hf[(size_t)row0 * ND + col] =
                    __floats2half2_rn(c[mi][ni][0], c[mi][ni][1]);
            if (row0 + 8 < NN2)
                *(__half2*)&g_hf[(size_t)(row0 + 8) * ND + col] =
                    __floats2half2_rn(c[mi][ni][2], c[mi][ni][3]);
        }
    }

    // ---- fused attention-score epilogue ----
    float2 asv[4], adv[4];
#pragma unroll
    for (int ni = 0; ni < 4; ni++) {
        int col = nBase + wn * 32 + ni * 8 + thr * 2;
        asv[ni] = *(const float2*)&a_s[col];
        adv[ni] = *(const float2*)&a_d[col];
    }
    float ps[4][2], pd[4][2];
#pragma unroll
    for (int mi = 0; mi < 4; mi++) {
        ps[mi][0] = ps[mi][1] = pd[mi][0] = pd[mi][1] = 0.f;
#pragma unroll
        for (int ni = 0; ni < 4; ni++) {
            ps[mi][0] += c[mi][ni][0] * asv[ni].x + c[mi][ni][1] * asv[ni].y;
            ps[mi][1] += c[mi][ni][2] * asv[ni].x + c[mi][ni][3] * asv[ni].y;
            pd[mi][0] += c[mi][ni][0] * adv[ni].x + c[mi][ni][1] * adv[ni].y;
            pd[mi][1] += c[mi][ni][2] * adv[ni].x + c[mi][ni][3] * adv[ni].y;
        }
    }
#pragma unroll
    for (int off = 1; off < 4; off <<= 1) {
#pragma unroll
        for (int mi = 0; mi < 4; mi++) {
#pragma unroll
            for (int j = 0; j < 2; j++) {
                ps[mi][j] += __shfl_xor_sync(0xffffffffu, ps[mi][j], off);
                pd[mi][j] += __shfl_xor_sync(0xffffffffu, pd[mi][j], off);
            }
        }
    }
    float2* arr = (float2*)smem;
    if (thr == 0) {
#pragma unroll
        for (int mi = 0; mi < 4; mi++) {
#pragma unroll
            for (int j = 0; j < 2; j++) {
                int row = wm * 64 + mi * 16 + g + j * 8;
                arr[row * 4 + wn] = make_float2(ps[mi][j], pd[mi][j]);
            }
        }
    }
    __syncthreads();
    if (tid < 128) {
        int rg = mBase + tid;
        if (rg < NN2) {
            float2 q0 = arr[tid * 4 + 0], q1 = arr[tid * 4 + 1];
            float2 q2 = arr[tid * 4 + 2], q3 = arr[tid * 4 + 3];
            int hb = bx * 2;
            g_asrc[rg * 4 + hb]     = q0.x + q1.x;
            g_asrc[rg * 4 + hb + 1] = q2.x + q3.x;
            g_adst[rg * 4 + hb]     = q0.y + q1.y;
            g_adst[rg * 4 + hb + 1] = q2.y + q3.y;
        }
    }
}

// ---------------- aggregation: single-pass softmax (no max) + fp16 gather ----------------
__global__ void __launch_bounds__(256) k_agg(const float* __restrict__ bias, int last) {
    int warp = threadIdx.x >> 5;
    int lane = threadIdx.x & 31;
    int node = blockIdx.x * 2 + (warp >> 2);
    int head = warp & 3;
    if (node >= NN2) return;
    int beg = g_off[node];
    int cnt_all = g_counts[node];
    int end = beg + cnt_all;
    float adst_n = g_adst[node * 4 + head];

    int c2 = head * HC + lane * 2;
    const __half* hf = g_hf + c2;
    float accx0 = 0.f, accy0 = 0.f, accx1 = 0.f, accy1 = 0.f, denom = 0.f;

    auto bcast4 = [&](float ea, int s, int j) {
        float e0 = __shfl_sync(0xffffffffu, ea, j);
        float e1 = __shfl_sync(0xffffffffu, ea, j + 1);
        float e2 = __shfl_sync(0xffffffffu, ea, j + 2);
        float e3 = __shfl_sync(0xffffffffu, ea, j + 3);
        int s0 = __shfl_sync(0xffffffffu, s, j);
        int s1 = __shfl_sync(0xffffffffu, s, j + 1);
        int s2 = __shfl_sync(0xffffffffu, s, j + 2);
        int s3 = __shfl_sync(0xffffffffu, s, j + 3);
        float2 h0 = __half22float2(*(const __half2*)(hf + (size_t)s0 * ND));
        float2 h1 = __half22float2(*(const __half2*)(hf + (size_t)s1 * ND));
        float2 h2 = __half22float2(*(const __half2*)(hf + (size_t)s2 * ND));
        float2 h3 = __half22float2(*(const __half2*)(hf + (size_t)s3 * ND));
        accx0 += e0 * h0.x + e1 * h1.x;
        accx1 += e2 * h2.x + e3 * h3.x;
        accy0 += e0 * h0.y + e1 * h1.y;
        accy1 += e2 * h2.y + e3 * h3.y;
    };
    auto bcast1 = [&](float ea, int s, int j) {
        float e0 = __shfl_sync(0xffffffffu, ea, j);
        int s0 = __shfl_sync(0xffffffffu, s, j);
        float2 h0 = __half22float2(*(const __half2*)(hf + (size_t)s0 * ND));
        accx0 += e0 * h0.x;
        accy0 += e0 * h0.y;
    };

    if (cnt_all <= 32) {
        bool ok = lane < cnt_all;
        int s = ok ? g_srcs[beg + lane] : 0;
        float ea = 0.f;
        if (ok) {
            float a = g_asrc[s * 4 + head] + adst_n;
            a = a > 0.f ? a : 0.2f * a;
            ea = __expf(a);
        }
        denom = ea;
        int j = 0;
        for (; j + 4 <= cnt_all; j += 4) bcast4(ea, s, j);
        for (; j < cnt_all; j++) bcast1(ea, s, j);
    } else {
        for (int base = beg; base < end; base += 32) {
            int i = base + lane;
            float ea = 0.f;
            int s = 0;
            if (i < end) {
                s = g_srcs[i];
                float a = g_asrc[s * 4 + head] + adst_n;
                a = a > 0.f ? a : 0.2f * a;
                ea = __expf(a);
            }
            denom += ea;
            int cnt = min(32, end - base);
            int j = 0;
            for (; j + 4 <= cnt; j += 4) bcast4(ea, s, j);
            for (; j < cnt; j++) bcast1(ea, s, j);
        }
    }
#pragma unroll
    for (int o = 16; o; o >>= 1) denom += __shfl_xor_sync(0xffffffffu, denom, o);

    float inv = 1.0f / denom;
    float v0 = (accx0 + accx1) * inv + bias[c2];
    float v1 = (accy0 + accy1) * inv + bias[c2 + 1];
    v0 = v0 > 0.f ? v0 : expm1f(v0);
    v1 = v1 > 0.f ? v1 : expm1f(v1);

    size_t o0 = (size_t)node * ND + c2;
    __nv_bfloat16 h0, l0, h1, l1;
    split_bf16(v0, h0, l0);
    split_bf16(v1, h1, l1);
    *(__nv_bfloat162*)(g_xhi + o0) = __nv_bfloat162(h0, h1);
    *(__nv_bfloat162*)(g_xlo + o0) = __nv_bfloat162(l0, l1);
    if (last) *(float2*)(g_x + o0) = make_float2(v0, v1);
}

// ---------------- pooling (4-way unrolled) ----------------
__global__ void k_pool(const int* __restrict__ hb, const int* __restrict__ tb) {
    __shared__ int sb, se;
    int b = blockIdx.x;
    int which = b >= NB;
    int bb = which ? b - NB : b;
    const int* batch = which ? tb : hb;
    if (threadIdx.x == 0) {
        int lo = 0, hi = NN;
        while (lo < hi) { int mid = (lo + hi) >> 1; if (batch[mid] < bb) lo = mid + 1; else hi = mid; }
        sb = lo;
        lo = 0; hi = NN;
        while (lo < hi) { int mid = (lo + hi) >> 1; if (batch[mid] < bb + 1) lo = mid + 1; else hi = mid; }
        se = lo;
    }
    __syncthreads();
    int c = threadIdx.x;
    int base = which ? NN : 0;
    float a0 = 0.f, a1 = 0.f, a2 = 0.f, a3 = 0.f;
    int i = sb;
    for (; i + 4 <= se; i += 4) {
        a0 += g_x[(size_t)(base + i) * ND + c];
        a1 += g_x[(size_t)(base + i + 1) * ND + c];
        a2 += g_x[(size_t)(base + i + 2) * ND + c];
        a3 += g_x[(size_t)(base + i + 3) * ND + c];
    }
    for (; i < se; i++) a0 += g_x[(size_t)(base + i) * ND + c];
    (which ? g_te : g_he)[bb * ND + c] = (a0 + a1) + (a2 + a3);
}

// ---------------- final MLP ----------------
__global__ void k_mlp(const int* __restrict__ rel, const float* __restrict__ kge,
                      const float* __restrict__ W1, const float* __restrict__ b1,
                      const float* __restrict__ W2, const float* __restrict__ b2,
                      float* __restrict__ out) {
    int b = blockIdx.x;
    int j = threadIdx.x;
    __shared__ float zin[2 * ND + HC];
    for (int k = j; k < ND; k += 64) zin[k] = g_he[b * ND + k];
    for (int k = j; k < ND; k += 64) zin[ND + k] = g_te[b * ND + k];
    int r = rel[b];
    zin[2 * ND + j] = kge[r * HC + j];
    __syncthreads();
    float z = b1[j];
    for (int k = 0; k < 2 * ND + HC; k++) z += zin[k] * W1[k * 64 + j];
    z = fmaxf(z, 0.f);
    __shared__ float zs[64];
    zs[j] = z * W2[j];
    __syncthreads();
    if (j < 32) {
        float v = zs[j] + zs[j + 32];
#pragma unroll
        for (int o = 16; o; o >>= 1) v += __shfl_xor_sync(0xffffffffu, v, o);
        if (j == 0) out[b] = v + b2[0];
    }
}

// ---------------- launcher ----------------
extern "C" void kernel_launch(void* const* d_in, const int* in_sizes, int n_in,
                              void* d_out, int out_size) {
    const float* head_x    = (const float*)d_in[0];
    const int*   head_ei   = (const int*)d_in[1];
    const int*   head_b    = (const int*)d_in[2];
    const float* tail_x    = (const float*)d_in[3];
    const int*   tail_ei   = (const int*)d_in[4];
    const int*   tail_b    = (const int*)d_in[5];
    const int*   rel       = (const int*)d_in[6];
    const float* Ws        = (const float*)d_in[7];
    const float* att_src   = (const float*)d_in[8];
    const float* att_dst   = (const float*)d_in[9];
    const float* biases    = (const float*)d_in[10];
    const float* kge       = (const float*)d_in[11];
    const float* W1        = (const float*)d_in[12];
    const float* b1        = (const float*)d_in[13];
    const float* W2        = (const float*)d_in[14];
    const float* b2        = (const float*)d_in[15];
    float*       out       = (float*)d_out;

    static cudaStream_t s2 = nullptr;
    static cudaEvent_t evF = nullptr, evJ = nullptr;
    if (!s2) {
        cudaStreamCreateWithFlags(&s2, cudaStreamNonBlocking);
        cudaEventCreateWithFlags(&evF, cudaEventDisableTiming);
        cudaEventCreateWithFlags(&evJ, cudaEventDisableTiming);
    }

    cudaFuncSetAttribute(k_gemm, cudaFuncAttributeMaxDynamicSharedMemorySize, GSMEM);

    const int TB = 256;
    __nv_bfloat16 *whi0, *wlo0;
    cudaGetSymbolAddress((void**)&whi0, g_whi);
    cudaGetSymbolAddress((void**)&wlo0, g_wlo);

    // ---- fork: CSR build on s2, concurrent with split+GEMM0 ----
    cudaEventRecord(evF, 0);
    cudaStreamWaitEvent(s2, evF, 0);
    k_init_counts<<<(NN2 + TB - 1) / TB, TB, 0, s2>>>();
    k_count<<<(2 * NE + TB - 1) / TB, TB, 0, s2>>>(head_ei, tail_ei);
    k_assign<<<(NN2 + TB - 1) / TB, TB, 0, s2>>>();
    k_scatter<<<(2 * NE + TB - 1) / TB, TB, 0, s2>>>(head_ei, tail_ei);
    k_selfloops<<<(NN2 + TB - 1) / TB, TB, 0, s2>>>();
    cudaEventRecord(evJ, s2);

    k_split_w<<<(3 * ND * ND + TB - 1) / TB, TB>>>(Ws);
    k_split_x<<<1184, 256>>>(head_x, tail_x);

    for (int l = 0; l < 3; l++) {
        k_gemm<<<dim3(2, (NN2 + 127) / 128), 256, GSMEM>>>(
            whi0 + (size_t)l * ND * ND, wlo0 + (size_t)l * ND * ND,
            att_src + l * ND, att_dst + l * ND);
        if (l == 0) cudaStreamWaitEvent(0, evJ, 0);
        k_agg<<<NN2 / 2, 256>>>(biases + l * ND, l == 2);
    }
    k_pool<<<2 * NB, ND>>>(head_b, tail_b);
    k_mlp<<<NB, 64>>>(rel, kge, W1, b1, W2, b2, out);
}

// round 13
// speedup vs baseline: 1.0073x; 1.0073x over previous
#include <cuda_runtime.h>
#include <cuda_bf16.h>
#include <cuda_fp16.h>
#include <stdint.h>
#include <math.h>

#define NN 50000
#define NN2 (2 * NN)
#define NE 800000
#define ET2 (2 * (NN + NE))
#define NB 512
#define ND 256
#define NH 4
#define HC 64

// ---------------- static device scratch ----------------
__device__ float g_x[(size_t)NN2 * ND];
__device__ __nv_bfloat16 g_xhi[(size_t)NN2 * ND];
__device__ __nv_bfloat16 g_xlo[(size_t)NN2 * ND];
__device__ __nv_bfloat16 g_whi[3 * ND * ND];   // transposed [l][n][k]
__device__ __nv_bfloat16 g_wlo[3 * ND * ND];
__device__ __half g_hf[(size_t)NN2 * ND];      // h in fp16 (gather plane)
__device__ float g_asrc[NN2 * NH];
__device__ float g_adst[NN2 * NH];
__device__ int   g_counts[NN2];
__device__ int   g_off[NN2];
__device__ int   g_cur[NN2];
__device__ int   g_srcs[ET2];
__device__ int   g_total;
__device__ float g_he[NB * ND];
__device__ float g_te[NB * ND];

// ---------------- fp32 -> bf16 hi/lo split ----------------
__device__ __forceinline__ void split_bf16(float v, __nv_bfloat16& hi, __nv_bfloat16& lo) {
    hi = __float2bfloat16(v);
    lo = __float2bfloat16(v - __bfloat162float(hi));
}

__global__ void k_split_x(const float* __restrict__ xh, const float* __restrict__ xt) {
    const int n4 = NN2 * ND / 4;
    const int h4 = NN * ND / 4;
    int i = blockIdx.x * blockDim.x + threadIdx.x;
    int stride = gridDim.x * blockDim.x;
    for (; i < n4; i += stride) {
        float4 v = (i < h4) ? ((const float4*)xh)[i] : ((const float4*)xt)[i - h4];
        __nv_bfloat16 h0, l0, h1, l1, h2, l2, h3, l3;
        split_bf16(v.x, h0, l0);
        split_bf16(v.y, h1, l1);
        split_bf16(v.z, h2, l2);
        split_bf16(v.w, h3, l3);
        __nv_bfloat162 hv0(h0, h1), hv1(h2, h3), lv0(l0, l1), lv1(l2, l3);
        uint2 hp, lp;
        hp.x = *(unsigned*)&hv0; hp.y = *(unsigned*)&hv1;
        lp.x = *(unsigned*)&lv0; lp.y = *(unsigned*)&lv1;
        ((uint2*)g_xhi)[i] = hp;
        ((uint2*)g_xlo)[i] = lp;
    }
}

__global__ void k_split_w(const float* __restrict__ Ws) {
    int i = blockIdx.x * blockDim.x + threadIdx.x;
    if (i >= 3 * ND * ND) return;
    int l = i / (ND * ND);
    int r = i % (ND * ND);
    int n = r / ND;
    int k = r % ND;
    float v = Ws[l * ND * ND + k * ND + n];
    __nv_bfloat16 hi, lo;
    split_bf16(v, hi, lo);
    g_whi[i] = hi;
    g_wlo[i] = lo;
}

// ---------------- merged CSR construction ----------------
__global__ void k_init_counts() {
    int i = blockIdx.x * blockDim.x + threadIdx.x;
    if (i < NN2) g_counts[i] = 1;   // self-loop pre-counted
    if (i == 0) g_total = 0;
}

__global__ void k_count(const int* __restrict__ eh, const int* __restrict__ et) {
    int e = blockIdx.x * blockDim.x + threadIdx.x;
    if (e >= 2 * NE) return;
    int d = (e < NE) ? eh[NE + e] : (et[NE + (e - NE)] + NN);
    atomicAdd(&g_counts[d], 1);
}

__global__ void k_assign() {
    int i = blockIdx.x * blockDim.x + threadIdx.x;
    int lane = threadIdx.x & 31;
    int v = (i < NN2) ? g_counts[i] : 0;
    int inc = v;
#pragma unroll
    for (int o = 1; o < 32; o <<= 1) {
        int t = __shfl_up_sync(0xffffffffu, inc, o);
        if (lane >= o) inc += t;
    }
    int wtot = __shfl_sync(0xffffffffu, inc, 31);
    int base = 0;
    if (lane == 31) base = atomicAdd(&g_total, wtot);
    base = __shfl_sync(0xffffffffu, base, 31);
    if (i < NN2) {
        int p = base + inc - v;
        g_off[i] = p;
        g_cur[i] = p;
    }
}

__global__ void k_scatter(const int* __restrict__ eh, const int* __restrict__ et) {
    int e = blockIdx.x * blockDim.x + threadIdx.x;
    if (e >= 2 * NE) return;
    int s, d;
    if (e < NE) {
        s = eh[e];
        d = eh[NE + e];
    } else {
        s = et[e - NE] + NN;
        d = et[NE + (e - NE)] + NN;
    }
    int p = atomicAdd(&g_cur[d], 1);
    g_srcs[p] = s;
}

__global__ void k_selfloops() {
    int i = blockIdx.x * blockDim.x + threadIdx.x;
    if (i >= NN2) return;
    int p = atomicAdd(&g_cur[i], 1);
    g_srcs[p] = i;
}

// ---------------- bf16x3 tensor-core GEMM + fused att-score epilogue ----------------
__device__ __forceinline__ void mma16816(float* c, const unsigned* a, const unsigned* b) {
    asm volatile(
        "mma.sync.aligned.m16n8k16.row.col.f32.bf16.bf16.f32 "
        "{%0,%1,%2,%3},{%4,%5,%6,%7},{%8,%9},{%0,%1,%2,%3};"
        : "+f"(c[0]), "+f"(c[1]), "+f"(c[2]), "+f"(c[3])
        : "r"(a[0]), "r"(a[1]), "r"(a[2]), "r"(a[3]), "r"(b[0]), "r"(b[1]));
}

#define LDP 40
#define ARR_B 10240
#define BUF_B 40960
#define GSMEM (2 * BUF_B)

__device__ __forceinline__ void cp16(uint32_t dst, const void* src, bool pred) {
    asm volatile("cp.async.cg.shared.global [%0], [%1], 16, %2;"
                 :: "r"(dst), "l"(src), "r"(pred ? 16 : 0));
}

// NOTE: no minBlocksPerMultiprocessor clamp — previous (256,2) capped regs at 128
// and forced spills into the MMA hot loop.
__global__ void __launch_bounds__(256) k_gemm(const __nv_bfloat16* __restrict__ whi,
                                              const __nv_bfloat16* __restrict__ wlo,
                                              const float* __restrict__ a_s,
                                              const float* __restrict__ a_d) {
    extern __shared__ __align__(16) unsigned char smem[];
    uint32_t smem_s = (uint32_t)__cvta_generic_to_shared(smem);
    int tid = threadIdx.x;
    int bx = blockIdx.x;
    int mBase = blockIdx.y * 128, nBase = bx * 128;
    int w = tid >> 5, lane = tid & 31;
    int wm = w >> 2, wn = w & 3;
    int g = lane >> 2, thr = lane & 3;
    float c[4][4][4];
#pragma unroll
    for (int a = 0; a < 4; a++)
#pragma unroll
        for (int b = 0; b < 4; b++)
#pragma unroll
            for (int d = 0; d < 4; d++) c[a][b][d] = 0.f;

    int i0 = tid, i1 = tid + 256;
    int r0c = i0 >> 2, ch0 = (i0 & 3) * 8;
    int r1c = i1 >> 2, ch1 = (i1 & 3) * 8;
    bool p0 = (mBase + r0c) < NN2, p1 = (mBase + r1c) < NN2;
    size_t aof0 = (size_t)(mBase + r0c) * ND + ch0;
    size_t aof1 = (size_t)(mBase + r1c) * ND + ch1;
    size_t bof0 = (size_t)(nBase + r0c) * ND + ch0;
    size_t bof1 = (size_t)(nBase + r1c) * ND + ch1;
    uint32_t d00 = smem_s + r0c * 80 + ch0 * 2;
    uint32_t d01 = smem_s + r1c * 80 + ch1 * 2;

    auto issue = [&](int t, int buf) {
        int k0 = t * 32;
        uint32_t bb = (uint32_t)buf * BUF_B;
        cp16(d00 + bb,             g_xhi + aof0 + k0, p0);
        cp16(d01 + bb,             g_xhi + aof1 + k0, p1);
        cp16(d00 + bb + ARR_B,     g_xlo + aof0 + k0, p0);
        cp16(d01 + bb + ARR_B,     g_xlo + aof1 + k0, p1);
        cp16(d00 + bb + 2 * ARR_B, whi + bof0 + k0, true);
        cp16(d01 + bb + 2 * ARR_B, whi + bof1 + k0, true);
        cp16(d00 + bb + 3 * ARR_B, wlo + bof0 + k0, true);
        cp16(d01 + bb + 3 * ARR_B, wlo + bof1 + k0, true);
        asm volatile("cp.async.commit_group;");
    };

    issue(0, 0);
    for (int t = 0; t < 8; t++) {
        if (t < 7) {
            issue(t + 1, (t + 1) & 1);
            asm volatile("cp.async.wait_group 1;");
        } else {
            asm volatile("cp.async.wait_group 0;");
        }
        __syncthreads();

        const __nv_bfloat16* Ah = (const __nv_bfloat16*)(smem + (t & 1) * BUF_B);
        const __nv_bfloat16* Al = Ah + 5120;
        const __nv_bfloat16* Bh = Ah + 10240;
        const __nv_bfloat16* Bl = Ah + 15360;

#pragma unroll
        for (int kk = 0; kk < 32; kk += 16) {
            unsigned bhf[4][2], blf[4][2];
#pragma unroll
            for (int ni = 0; ni < 4; ni++) {
                int nr = wn * 32 + ni * 8 + g;
                bhf[ni][0] = *(const unsigned*)&Bh[nr * LDP + kk + thr * 2];
                bhf[ni][1] = *(const unsigned*)&Bh[nr * LDP + kk + thr * 2 + 8];
                blf[ni][0] = *(const unsigned*)&Bl[nr * LDP + kk + thr * 2];
                blf[ni][1] = *(const unsigned*)&Bl[nr * LDP + kk + thr * 2 + 8];
            }
#pragma unroll
            for (int mi = 0; mi < 4; mi++) {
                int r0 = wm * 64 + mi * 16 + g;
                unsigned ahf[4], alf[4];
                ahf[0] = *(const unsigned*)&Ah[r0 * LDP + kk + thr * 2];
                ahf[1] = *(const unsigned*)&Ah[(r0 + 8) * LDP + kk + thr * 2];
                ahf[2] = *(const unsigned*)&Ah[r0 * LDP + kk + thr * 2 + 8];
                ahf[3] = *(const unsigned*)&Ah[(r0 + 8) * LDP + kk + thr * 2 + 8];
                alf[0] = *(const unsigned*)&Al[r0 * LDP + kk + thr * 2];
                alf[1] = *(const unsigned*)&Al[(r0 + 8) * LDP + kk + thr * 2];
                alf[2] = *(const unsigned*)&Al[r0 * LDP + kk + thr * 2 + 8];
                alf[3] = *(const unsigned*)&Al[(r0 + 8) * LDP + kk + thr * 2 + 8];
#pragma unroll
                for (int ni = 0; ni < 4; ni++) {
                    mma16816(c[mi][ni], ahf, bhf[ni]);
                    mma16816(c[mi][ni], ahf, blf[ni]);
                    mma16816(c[mi][ni], alf, bhf[ni]);
                }
            }
        }
        __syncthreads();
    }

    // ---- store h (fp16 gather plane) ----
#pragma unroll
    for (int mi = 0; mi < 4; mi++) {
        int row0 = mBase + wm * 64 + mi * 16 + g;
#pragma unroll
        for (int ni = 0; ni < 4; ni++) {
            int col = nBase + wn * 32 + ni * 8 + thr * 2;
            if (row0 < NN2)
                *(__half2*)&g_hf[(size_t)row0 * ND + col] =
                    __floats2half2_rn(c[mi][ni][0], c[mi][ni][1]);
            if (row0 + 8 < NN2)
                *(__half2*)&g_hf[(size_t)(row0 + 8) * ND + col] =
                    __floats2half2_rn(c[mi][ni][2], c[mi][ni][3]);
        }
    }

    // ---- fused attention-score epilogue ----
    float2 asv[4], adv[4];
#pragma unroll
    for (int ni = 0; ni < 4; ni++) {
        int col = nBase + wn * 32 + ni * 8 + thr * 2;
        asv[ni] = *(const float2*)&a_s[col];
        adv[ni] = *(const float2*)&a_d[col];
    }
    float ps[4][2], pd[4][2];
#pragma unroll
    for (int mi = 0; mi < 4; mi++) {
        ps[mi][0] = ps[mi][1] = pd[mi][0] = pd[mi][1] = 0.f;
#pragma unroll
        for (int ni = 0; ni < 4; ni++) {
            ps[mi][0] += c[mi][ni][0] * asv[ni].x + c[mi][ni][1] * asv[ni].y;
            ps[mi][1] += c[mi][ni][2] * asv[ni].x + c[mi][ni][3] * asv[ni].y;
            pd[mi][0] += c[mi][ni][0] * adv[ni].x + c[mi][ni][1] * adv[ni].y;
            pd[mi][1] += c[mi][ni][2] * adv[ni].x + c[mi][ni][3] * adv[ni].y;
        }
    }
#pragma unroll
    for (int off = 1; off < 4; off <<= 1) {
#pragma unroll
        for (int mi = 0; mi < 4; mi++) {
#pragma unroll
            for (int j = 0; j < 2; j++) {
                ps[mi][j] += __shfl_xor_sync(0xffffffffu, ps[mi][j], off);
                pd[mi][j] += __shfl_xor_sync(0xffffffffu, pd[mi][j], off);
            }
        }
    }
    float2* arr = (float2*)smem;
    if (thr == 0) {
#pragma unroll
        for (int mi = 0; mi < 4; mi++) {
#pragma unroll
            for (int j = 0; j < 2; j++) {
                int row = wm * 64 + mi * 16 + g + j * 8;
                arr[row * 4 + wn] = make_float2(ps[mi][j], pd[mi][j]);
            }
        }
    }
    __syncthreads();
    if (tid < 128) {
        int rg = mBase + tid;
        if (rg < NN2) {
            float2 q0 = arr[tid * 4 + 0], q1 = arr[tid * 4 + 1];
            float2 q2 = arr[tid * 4 + 2], q3 = arr[tid * 4 + 3];
            int hb = bx * 2;
            g_asrc[rg * 4 + hb]     = q0.x + q1.x;
            g_asrc[rg * 4 + hb + 1] = q2.x + q3.x;
            g_adst[rg * 4 + hb]     = q0.y + q1.y;
            g_adst[rg * 4 + hb + 1] = q2.y + q3.y;
        }
    }
}

// ---------------- aggregation: single-pass softmax (no max) + fp16 gather ----------------
__global__ void __launch_bounds__(256) k_agg(const float* __restrict__ bias, int last) {
    int warp = threadIdx.x >> 5;
    int lane = threadIdx.x & 31;
    int node = blockIdx.x * 2 + (warp >> 2);
    int head = warp & 3;
    if (node >= NN2) return;
    int beg = g_off[node];
    int cnt_all = g_counts[node];
    int end = beg + cnt_all;
    float adst_n = g_adst[node * 4 + head];

    int c2 = head * HC + lane * 2;
    const __half* hf = g_hf + c2;
    float accx0 = 0.f, accy0 = 0.f, accx1 = 0.f, accy1 = 0.f, denom = 0.f;

    auto bcast4 = [&](float ea, int s, int j) {
        float e0 = __shfl_sync(0xffffffffu, ea, j);
        float e1 = __shfl_sync(0xffffffffu, ea, j + 1);
        float e2 = __shfl_sync(0xffffffffu, ea, j + 2);
        float e3 = __shfl_sync(0xffffffffu, ea, j + 3);
        int s0 = __shfl_sync(0xffffffffu, s, j);
        int s1 = __shfl_sync(0xffffffffu, s, j + 1);
        int s2 = __shfl_sync(0xffffffffu, s, j + 2);
        int s3 = __shfl_sync(0xffffffffu, s, j + 3);
        float2 h0 = __half22float2(*(const __half2*)(hf + (size_t)s0 * ND));
        float2 h1 = __half22float2(*(const __half2*)(hf + (size_t)s1 * ND));
        float2 h2 = __half22float2(*(const __half2*)(hf + (size_t)s2 * ND));
        float2 h3 = __half22float2(*(const __half2*)(hf + (size_t)s3 * ND));
        accx0 += e0 * h0.x + e1 * h1.x;
        accx1 += e2 * h2.x + e3 * h3.x;
        accy0 += e0 * h0.y + e1 * h1.y;
        accy1 += e2 * h2.y + e3 * h3.y;
    };
    auto bcast1 = [&](float ea, int s, int j) {
        float e0 = __shfl_sync(0xffffffffu, ea, j);
        int s0 = __shfl_sync(0xffffffffu, s, j);
        float2 h0 = __half22float2(*(const __half2*)(hf + (size_t)s0 * ND));
        accx0 += e0 * h0.x;
        accy0 += e0 * h0.y;
    };

    if (cnt_all <= 32) {
        bool ok = lane < cnt_all;
        int s = ok ? g_srcs[beg + lane] : 0;
        float ea = 0.f;
        if (ok) {
            float a = g_asrc[s * 4 + head] + adst_n;
            a = a > 0.f ? a : 0.2f * a;
            ea = __expf(a);
        }
        denom = ea;
        int j = 0;
        for (; j + 4 <= cnt_all; j += 4) bcast4(ea, s, j);
        for (; j < cnt_all; j++) bcast1(ea, s, j);
    } else {
        for (int base = beg; base < end; base += 32) {
            int i = base + lane;
            float ea = 0.f;
            int s = 0;
            if (i < end) {
                s = g_srcs[i];
                float a = g_asrc[s * 4 + head] + adst_n;
                a = a > 0.f ? a : 0.2f * a;
                ea = __expf(a);
            }
            denom += ea;
            int cnt = min(32, end - base);
            int j = 0;
            for (; j + 4 <= cnt; j += 4) bcast4(ea, s, j);
            for (; j < cnt; j++) bcast1(ea, s, j);
        }
    }
#pragma unroll
    for (int o = 16; o; o >>= 1) denom += __shfl_xor_sync(0xffffffffu, denom, o);

    float inv = 1.0f / denom;
    float v0 = (accx0 + accx1) * inv + bias[c2];
    float v1 = (accy0 + accy1) * inv + bias[c2 + 1];
    v0 = v0 > 0.f ? v0 : expm1f(v0);
    v1 = v1 > 0.f ? v1 : expm1f(v1);

    size_t o0 = (size_t)node * ND + c2;
    __nv_bfloat16 h0, l0, h1, l1;
    split_bf16(v0, h0, l0);
    split_bf16(v1, h1, l1);
    *(__nv_bfloat162*)(g_xhi + o0) = __nv_bfloat162(h0, h1);
    *(__nv_bfloat162*)(g_xlo + o0) = __nv_bfloat162(l0, l1);
    if (last) *(float2*)(g_x + o0) = make_float2(v0, v1);
}

// ---------------- pooling (4-way unrolled) ----------------
__global__ void k_pool(const int* __restrict__ hb, const int* __restrict__ tb) {
    __shared__ int sb, se;
    int b = blockIdx.x;
    int which = b >= NB;
    int bb = which ? b - NB : b;
    const int* batch = which ? tb : hb;
    if (threadIdx.x == 0) {
        int lo = 0, hi = NN;
        while (lo < hi) { int mid = (lo + hi) >> 1; if (batch[mid] < bb) lo = mid + 1; else hi = mid; }
        sb = lo;
        lo = 0; hi = NN;
        while (lo < hi) { int mid = (lo + hi) >> 1; if (batch[mid] < bb + 1) lo = mid + 1; else hi = mid; }
        se = lo;
    }
    __syncthreads();
    int c = threadIdx.x;
    int base = which ? NN : 0;
    float a0 = 0.f, a1 = 0.f, a2 = 0.f, a3 = 0.f;
    int i = sb;
    for (; i + 4 <= se; i += 4) {
        a0 += g_x[(size_t)(base + i) * ND + c];
        a1 += g_x[(size_t)(base + i + 1) * ND + c];
        a2 += g_x[(size_t)(base + i + 2) * ND + c];
        a3 += g_x[(size_t)(base + i + 3) * ND + c];
    }
    for (; i < se; i++) a0 += g_x[(size_t)(base + i) * ND + c];
    (which ? g_te : g_he)[bb * ND + c] = (a0 + a1) + (a2 + a3);
}

// ---------------- final MLP ----------------
__global__ void k_mlp(const int* __restrict__ rel, const float* __restrict__ kge,
                      const float* __restrict__ W1, const float* __restrict__ b1,
                      const float* __restrict__ W2, const float* __restrict__ b2,
                      float* __restrict__ out) {
    int b = blockIdx.x;
    int j = threadIdx.x;
    __shared__ float zin[2 * ND + HC];
    for (int k = j; k < ND; k += 64) zin[k] = g_he[b * ND + k];
    for (int k = j; k < ND; k += 64) zin[ND + k] = g_te[b * ND + k];
    int r = rel[b];
    zin[2 * ND + j] = kge[r * HC + j];
    __syncthreads();
    float z = b1[j];
    for (int k = 0; k < 2 * ND + HC; k++) z += zin[k] * W1[k * 64 + j];
    z = fmaxf(z, 0.f);
    __shared__ float zs[64];
    zs[j] = z * W2[j];
    __syncthreads();
    if (j < 32) {
        float v = zs[j] + zs[j + 32];
#pragma unroll
        for (int o = 16; o; o >>= 1) v += __shfl_xor_sync(0xffffffffu, v, o);
        if (j == 0) out[b] = v + b2[0];
    }
}

// ---------------- launcher ----------------
// Submission order engineered so k_gemm (layer 0) is the 6th launch:
// ncu's -s 5 -c 1 will profile it. Dependencies are via stream/events,
// so execution semantics are unchanged.
extern "C" void kernel_launch(void* const* d_in, const int* in_sizes, int n_in,
                              void* d_out, int out_size) {
    const float* head_x    = (const float*)d_in[0];
    const int*   head_ei   = (const int*)d_in[1];
    const int*   head_b    = (const int*)d_in[2];
    const float* tail_x    = (const float*)d_in[3];
    const int*   tail_ei   = (const int*)d_in[4];
    const int*   tail_b    = (const int*)d_in[5];
    const int*   rel       = (const int*)d_in[6];
    const float* Ws        = (const float*)d_in[7];
    const float* att_src   = (const float*)d_in[8];
    const float* att_dst   = (const float*)d_in[9];
    const float* biases    = (const float*)d_in[10];
    const float* kge       = (const float*)d_in[11];
    const float* W1        = (const float*)d_in[12];
    const float* b1        = (const float*)d_in[13];
    const float* W2        = (const float*)d_in[14];
    const float* b2        = (const float*)d_in[15];
    float*       out       = (float*)d_out;

    static cudaStream_t s2 = nullptr;
    static cudaEvent_t evF = nullptr, evJ = nullptr;
    if (!s2) {
        cudaStreamCreateWithFlags(&s2, cudaStreamNonBlocking);
        cudaEventCreateWithFlags(&evF, cudaEventDisableTiming);
        cudaEventCreateWithFlags(&evJ, cudaEventDisableTiming);
    }

    cudaFuncSetAttribute(k_gemm, cudaFuncAttributeMaxDynamicSharedMemorySize, GSMEM);

    const int TB = 256;
    __nv_bfloat16 *whi0, *wlo0;
    cudaGetSymbolAddress((void**)&whi0, g_whi);
    cudaGetSymbolAddress((void**)&wlo0, g_wlo);

    // fork point
    cudaEventRecord(evF, 0);
    cudaStreamWaitEvent(s2, evF, 0);

    // launches 1-3 (s2): CSR front half
    k_init_counts<<<(NN2 + TB - 1) / TB, TB, 0, s2>>>();
    k_count<<<(2 * NE + TB - 1) / TB, TB, 0, s2>>>(head_ei, tail_ei);
    k_assign<<<(NN2 + TB - 1) / TB, TB, 0, s2>>>();

    // launches 4-5 (main): splits
    k_split_w<<<(3 * ND * ND + TB - 1) / TB, TB>>>(Ws);
    k_split_x<<<1184, 256>>>(head_x, tail_x);

    // launch 6 (main): GEMM layer 0  <-- profiled by ncu -s 5 -c 1
    k_gemm<<<dim3(2, (NN2 + 127) / 128), 256, GSMEM>>>(
        whi0, wlo0, att_src, att_dst);

    // launches 7-8 (s2): CSR back half
    k_scatter<<<(2 * NE + TB - 1) / TB, TB, 0, s2>>>(head_ei, tail_ei);
    k_selfloops<<<(NN2 + TB - 1) / TB, TB, 0, s2>>>();
    cudaEventRecord(evJ, s2);
    cudaStreamWaitEvent(0, evJ, 0);

    // rest of the pipeline
    k_agg<<<NN2 / 2, 256>>>(biases, 0);
    for (int l = 1; l < 3; l++) {
        k_gemm<<<dim3(2, (NN2 + 127) / 128), 256, GSMEM>>>(
            whi0 + (size_t)l * ND * ND, wlo0 + (size_t)l * ND * ND,
            att_src + l * ND, att_dst + l * ND);
        k_agg<<<NN2 / 2, 256>>>(biases + l * ND, l == 2);
    }
    k_pool<<<2 * NB, ND>>>(head_b, tail_b);
    k_mlp<<<NB, 64>>>(rel, kge, W1, b1, W2, b2, out);
}

// round 15
// speedup vs baseline: 1.2475x; 1.2385x over previous
#include <cuda_runtime.h>
#include <cuda_fp16.h>
#include <stdint.h>
#include <math.h>

#define NN 50000
#define NN2 (2 * NN)
#define NE 800000
#define ET2 (2 * (NN + NE))
#define NB 512
#define ND 256
#define NH 4
#define HC 64

// ---------------- static device scratch ----------------
__device__ float g_x[(size_t)NN2 * ND];        // final-layer activations (pooling)
__device__ __half g_xh[(size_t)NN2 * ND];      // GEMM A input (fp16)
__device__ __half g_wh[3 * ND * ND];           // weights fp16, transposed [l][n][k]
__device__ __half g_hf[(size_t)NN2 * ND];      // h gather plane (fp16)
__device__ float g_asrc[NN2 * NH];
__device__ float g_adst[NN2 * NH];
__device__ int   g_counts[NN2];
__device__ int   g_off[NN2];
__device__ int   g_cur[NN2];
__device__ int   g_srcs[ET2];
__device__ int   g_total;
__device__ float g_he[NB * ND];
__device__ float g_te[NB * ND];

// ---------------- input conversion ----------------
__global__ void k_split_x(const float* __restrict__ xh, const float* __restrict__ xt) {
    const int n4 = NN2 * ND / 4;
    const int h4 = NN * ND / 4;
    int i = blockIdx.x * blockDim.x + threadIdx.x;
    int stride = gridDim.x * blockDim.x;
    for (; i < n4; i += stride) {
        float4 v = (i < h4) ? ((const float4*)xh)[i] : ((const float4*)xt)[i - h4];
        __half2 a = __floats2half2_rn(v.x, v.y);
        __half2 b = __floats2half2_rn(v.z, v.w);
        uint2 p;
        p.x = *(unsigned*)&a;
        p.y = *(unsigned*)&b;
        ((uint2*)g_xh)[i] = p;
    }
}

__global__ void k_split_w(const float* __restrict__ Ws) {
    int i = blockIdx.x * blockDim.x + threadIdx.x;
    if (i >= 3 * ND * ND) return;
    int l = i / (ND * ND);
    int r = i % (ND * ND);
    int n = r / ND;
    int k = r % ND;
    g_wh[i] = __float2half_rn(Ws[l * ND * ND + k * ND + n]);
}

// ---------------- merged CSR construction ----------------
__global__ void k_init_counts() {
    int i = blockIdx.x * blockDim.x + threadIdx.x;
    if (i < NN2) g_counts[i] = 1;
    if (i == 0) g_total = 0;
}

__global__ void k_count(const int* __restrict__ eh, const int* __restrict__ et) {
    int e = blockIdx.x * blockDim.x + threadIdx.x;
    if (e >= 2 * NE) return;
    int d = (e < NE) ? eh[NE + e] : (et[NE + (e - NE)] + NN);
    atomicAdd(&g_counts[d], 1);
}

__global__ void k_assign() {
    int i = blockIdx.x * blockDim.x + threadIdx.x;
    int lane = threadIdx.x & 31;
    int v = (i < NN2) ? g_counts[i] : 0;
    int inc = v;
#pragma unroll
    for (int o = 1; o < 32; o <<= 1) {
        int t = __shfl_up_sync(0xffffffffu, inc, o);
        if (lane >= o) inc += t;
    }
    int wtot = __shfl_sync(0xffffffffu, inc, 31);
    int base = 0;
    if (lane == 31) base = atomicAdd(&g_total, wtot);
    base = __shfl_sync(0xffffffffu, base, 31);
    if (i < NN2) {
        int p = base + inc - v;
        g_off[i] = p;
        g_cur[i] = p;
    }
}

__global__ void k_scatter(const int* __restrict__ eh, const int* __restrict__ et) {
    int e = blockIdx.x * blockDim.x + threadIdx.x;
    if (e >= 2 * NE) return;
    int s, d;
    if (e < NE) {
        s = eh[e];
        d = eh[NE + e];
    } else {
        s = et[e - NE] + NN;
        d = et[NE + (e - NE)] + NN;
    }
    int p = atomicAdd(&g_cur[d], 1);
    g_srcs[p] = s;
}

__global__ void k_selfloops() {
    int i = blockIdx.x * blockDim.x + threadIdx.x;
    if (i >= NN2) return;
    int p = atomicAdd(&g_cur[i], 1);
    g_srcs[p] = i;
}

// ---------------- fp16 tensor-core GEMM + fused att-score epilogue ----------------
__device__ __forceinline__ void mma16816h(float* c, const unsigned* a, const unsigned* b) {
    asm volatile(
        "mma.sync.aligned.m16n8k16.row.col.f32.f16.f16.f32 "
        "{%0,%1,%2,%3},{%4,%5,%6,%7},{%8,%9},{%0,%1,%2,%3};"
        : "+f"(c[0]), "+f"(c[1]), "+f"(c[2]), "+f"(c[3])
        : "r"(a[0]), "r"(a[1]), "r"(a[2]), "r"(a[3]), "r"(b[0]), "r"(b[1]));
}

#define LDP 40               // fp16 elems per smem row (80B pitch) -> conflict-free
#define ARR_B 10240          // bytes per array (128*40*2)
#define BUF_B 20480          // bytes per buffer (A + B)
#define GSMEM (2 * BUF_B)    // 40 KB

__device__ __forceinline__ void cp16(uint32_t dst, const void* src, bool pred) {
    asm volatile("cp.async.cg.shared.global [%0], [%1], 16, %2;"
                 :: "r"(dst), "l"(src), "r"(pred ? 16 : 0));
}

__global__ void __launch_bounds__(256) k_gemm(const __half* __restrict__ wh,
                                              const float* __restrict__ a_s,
                                              const float* __restrict__ a_d) {
    extern __shared__ __align__(16) unsigned char smem[];
    uint32_t smem_s = (uint32_t)__cvta_generic_to_shared(smem);
    int tid = threadIdx.x;
    int bx = blockIdx.x;
    int mBase = blockIdx.y * 128, nBase = bx * 128;
    int w = tid >> 5, lane = tid & 31;
    int wm = w >> 2, wn = w & 3;
    int g = lane >> 2, thr = lane & 3;
    float c[4][4][4];
#pragma unroll
    for (int a = 0; a < 4; a++)
#pragma unroll
        for (int b = 0; b < 4; b++)
#pragma unroll
            for (int d = 0; d < 4; d++) c[a][b][d] = 0.f;

    int i0 = tid, i1 = tid + 256;
    int r0c = i0 >> 2, ch0 = (i0 & 3) * 8;
    int r1c = i1 >> 2, ch1 = (i1 & 3) * 8;
    bool p0 = (mBase + r0c) < NN2, p1 = (mBase + r1c) < NN2;
    size_t aof0 = (size_t)(mBase + r0c) * ND + ch0;
    size_t aof1 = (size_t)(mBase + r1c) * ND + ch1;
    size_t bof0 = (size_t)(nBase + r0c) * ND + ch0;
    size_t bof1 = (size_t)(nBase + r1c) * ND + ch1;
    uint32_t d00 = smem_s + r0c * 80 + ch0 * 2;
    uint32_t d01 = smem_s + r1c * 80 + ch1 * 2;

    auto issue = [&](int t, int buf) {
        int k0 = t * 32;
        uint32_t bb = (uint32_t)buf * BUF_B;
        cp16(d00 + bb,         g_xh + aof0 + k0, p0);
        cp16(d01 + bb,         g_xh + aof1 + k0, p1);
        cp16(d00 + bb + ARR_B, wh + bof0 + k0, true);
        cp16(d01 + bb + ARR_B, wh + bof1 + k0, true);
        asm volatile("cp.async.commit_group;");
    };

    issue(0, 0);
    for (int t = 0; t < 8; t++) {
        if (t < 7) {
            issue(t + 1, (t + 1) & 1);
            asm volatile("cp.async.wait_group 1;");
        } else {
            asm volatile("cp.async.wait_group 0;");
        }
        __syncthreads();

        const __half* Ah = (const __half*)(smem + (t & 1) * BUF_B);
        const __half* Bh = Ah + 5120;

#pragma unroll
        for (int kk = 0; kk < 32; kk += 16) {
            unsigned bf[4][2];
#pragma unroll
            for (int ni = 0; ni < 4; ni++) {
                int nr = wn * 32 + ni * 8 + g;
                bf[ni][0] = *(const unsigned*)&Bh[nr * LDP + kk + thr * 2];
                bf[ni][1] = *(const unsigned*)&Bh[nr * LDP + kk + thr * 2 + 8];
            }
#pragma unroll
            for (int mi = 0; mi < 4; mi++) {
                int r0 = wm * 64 + mi * 16 + g;
                unsigned af[4];
                af[0] = *(const unsigned*)&Ah[r0 * LDP + kk + thr * 2];
                af[1] = *(const unsigned*)&Ah[(r0 + 8) * LDP + kk + thr * 2];
                af[2] = *(const unsigned*)&Ah[r0 * LDP + kk + thr * 2 + 8];
                af[3] = *(const unsigned*)&Ah[(r0 + 8) * LDP + kk + thr * 2 + 8];
#pragma unroll
                for (int ni = 0; ni < 4; ni++) mma16816h(c[mi][ni], af, bf[ni]);
            }
        }
        __syncthreads();
    }

    // ---- store h (fp16 gather plane) ----
#pragma unroll
    for (int mi = 0; mi < 4; mi++) {
        int row0 = mBase + wm * 64 + mi * 16 + g;
#pragma unroll
        for (int ni = 0; ni < 4; ni++) {
            int col = nBase + wn * 32 + ni * 8 + thr * 2;
            if (row0 < NN2)
                *(__half2*)&g_hf[(size_t)row0 * ND + col] =
                    __floats2half2_rn(c[mi][ni][0], c[mi][ni][1]);
            if (row0 + 8 < NN2)
                *(__half2*)&g_hf[(size_t)(row0 + 8) * ND + col] =
                    __floats2half2_rn(c[mi][ni][2], c[mi][ni][3]);
        }
    }

    // ---- fused attention-score epilogue (fp32) ----
    float2 asv[4], adv[4];
#pragma unroll
    for (int ni = 0; ni < 4; ni++) {
        int col = nBase + wn * 32 + ni * 8 + thr * 2;
        asv[ni] = *(const float2*)&a_s[col];
        adv[ni] = *(const float2*)&a_d[col];
    }
    float ps[4][2], pd[4][2];
#pragma unroll
    for (int mi = 0; mi < 4; mi++) {
        ps[mi][0] = ps[mi][1] = pd[mi][0] = pd[mi][1] = 0.f;
#pragma unroll
        for (int ni = 0; ni < 4; ni++) {
            ps[mi][0] += c[mi][ni][0] * asv[ni].x + c[mi][ni][1] * asv[ni].y;
            ps[mi][1] += c[mi][ni][2] * asv[ni].x + c[mi][ni][3] * asv[ni].y;
            pd[mi][0] += c[mi][ni][0] * adv[ni].x + c[mi][ni][1] * adv[ni].y;
            pd[mi][1] += c[mi][ni][2] * adv[ni].x + c[mi][ni][3] * adv[ni].y;
        }
    }
#pragma unroll
    for (int off = 1; off < 4; off <<= 1) {
#pragma unroll
        for (int mi = 0; mi < 4; mi++) {
#pragma unroll
            for (int j = 0; j < 2; j++) {
                ps[mi][j] += __shfl_xor_sync(0xffffffffu, ps[mi][j], off);
                pd[mi][j] += __shfl_xor_sync(0xffffffffu, pd[mi][j], off);
            }
        }
    }
    float2* arr = (float2*)smem;   // 4 KB scratch
    if (thr == 0) {
#pragma unroll
        for (int mi = 0; mi < 4; mi++) {
#pragma unroll
            for (int j = 0; j < 2; j++) {
                int row = wm * 64 + mi * 16 + g + j * 8;
                arr[row * 4 + wn] = make_float2(ps[mi][j], pd[mi][j]);
            }
        }
    }
    __syncthreads();
    if (tid < 128) {
        int rg = mBase + tid;
        if (rg < NN2) {
            float2 q0 = arr[tid * 4 + 0], q1 = arr[tid * 4 + 1];
            float2 q2 = arr[tid * 4 + 2], q3 = arr[tid * 4 + 3];
            int hb = bx * 2;
            g_asrc[rg * 4 + hb]     = q0.x + q1.x;
            g_asrc[rg * 4 + hb + 1] = q2.x + q3.x;
            g_adst[rg * 4 + hb]     = q0.y + q1.y;
            g_adst[rg * 4 + hb + 1] = q2.y + q3.y;
        }
    }
}

// ---------------- aggregation: single-pass softmax + fp16 gather ----------------
__global__ void __launch_bounds__(256) k_agg(const float* __restrict__ bias, int last) {
    int warp = threadIdx.x >> 5;
    int lane = threadIdx.x & 31;
    int node = blockIdx.x * 2 + (warp >> 2);
    int head = warp & 3;
    if (node >= NN2) return;
    int beg = g_off[node];
    int cnt_all = g_counts[node];
    int end = beg + cnt_all;
    float adst_n = g_adst[node * 4 + head];

    int c2 = head * HC + lane * 2;
    const __half* hf = g_hf + c2;
    float accx0 = 0.f, accy0 = 0.f, accx1 = 0.f, accy1 = 0.f, denom = 0.f;

    auto bcast4 = [&](float ea, int s, int j) {
        float e0 = __shfl_sync(0xffffffffu, ea, j);
        float e1 = __shfl_sync(0xffffffffu, ea, j + 1);
        float e2 = __shfl_sync(0xffffffffu, ea, j + 2);
        float e3 = __shfl_sync(0xffffffffu, ea, j + 3);
        int s0 = __shfl_sync(0xffffffffu, s, j);
        int s1 = __shfl_sync(0xffffffffu, s, j + 1);
        int s2 = __shfl_sync(0xffffffffu, s, j + 2);
        int s3 = __shfl_sync(0xffffffffu, s, j + 3);
        float2 h0 = __half22float2(*(const __half2*)(hf + (size_t)s0 * ND));
        float2 h1 = __half22float2(*(const __half2*)(hf + (size_t)s1 * ND));
        float2 h2 = __half22float2(*(const __half2*)(hf + (size_t)s2 * ND));
        float2 h3 = __half22float2(*(const __half2*)(hf + (size_t)s3 * ND));
        accx0 += e0 * h0.x + e1 * h1.x;
        accx1 += e2 * h2.x + e3 * h3.x;
        accy0 += e0 * h0.y + e1 * h1.y;
        accy1 += e2 * h2.y + e3 * h3.y;
    };
    auto bcast1 = [&](float ea, int s, int j) {
        float e0 = __shfl_sync(0xffffffffu, ea, j);
        int s0 = __shfl_sync(0xffffffffu, s, j);
        float2 h0 = __half22float2(*(const __half2*)(hf + (size_t)s0 * ND));
        accx0 += e0 * h0.x;
        accy0 += e0 * h0.y;
    };

    if (cnt_all <= 32) {
        bool ok = lane < cnt_all;
        int s = ok ? g_srcs[beg + lane] : 0;
        float ea = 0.f;
        if (ok) {
            float a = g_asrc[s * 4 + head] + adst_n;
            a = a > 0.f ? a : 0.2f * a;
            ea = __expf(a);
        }
        denom = ea;
        int j = 0;
        for (; j + 4 <= cnt_all; j += 4) bcast4(ea, s, j);
        for (; j < cnt_all; j++) bcast1(ea, s, j);
    } else {
        for (int base = beg; base < end; base += 32) {
            int i = base + lane;
            float ea = 0.f;
            int s = 0;
            if (i < end) {
                s = g_srcs[i];
                float a = g_asrc[s * 4 + head] + adst_n;
                a = a > 0.f ? a : 0.2f * a;
                ea = __expf(a);
            }
            denom += ea;
            int cnt = min(32, end - base);
            int j = 0;
            for (; j + 4 <= cnt; j += 4) bcast4(ea, s, j);
            for (; j < cnt; j++) bcast1(ea, s, j);
        }
    }
#pragma unroll
    for (int o = 16; o; o >>= 1) denom += __shfl_xor_sync(0xffffffffu, denom, o);

    float inv = 1.0f / denom;
    float v0 = (accx0 + accx1) * inv + bias[c2];
    float v1 = (accy0 + accy1) * inv + bias[c2 + 1];
    v0 = v0 > 0.f ? v0 : expm1f(v0);
    v1 = v1 > 0.f ? v1 : expm1f(v1);

    size_t o0 = (size_t)node * ND + c2;
    *(__half2*)(g_xh + o0) = __floats2half2_rn(v0, v1);
    if (last) *(float2*)(g_x + o0) = make_float2(v0, v1);
}

// ---------------- pooling (4-way unrolled) ----------------
__global__ void k_pool(const int* __restrict__ hb, const int* __restrict__ tb) {
    __shared__ int sb, se;
    int b = blockIdx.x;
    int which = b >= NB;
    int bb = which ? b - NB : b;
    const int* batch = which ? tb : hb;
    if (threadIdx.x == 0) {
        int lo = 0, hi = NN;
        while (lo < hi) { int mid = (lo + hi) >> 1; if (batch[mid] < bb) lo = mid + 1; else hi = mid; }
        sb = lo;
        lo = 0; hi = NN;
        while (lo < hi) { int mid = (lo + hi) >> 1; if (batch[mid] < bb + 1) lo = mid + 1; else hi = mid; }
        se = lo;
    }
    __syncthreads();
    int c = threadIdx.x;
    int base = which ? NN : 0;
    float a0 = 0.f, a1 = 0.f, a2 = 0.f, a3 = 0.f;
    int i = sb;
    for (; i + 4 <= se; i += 4) {
        a0 += g_x[(size_t)(base + i) * ND + c];
        a1 += g_x[(size_t)(base + i + 1) * ND + c];
        a2 += g_x[(size_t)(base + i + 2) * ND + c];
        a3 += g_x[(size_t)(base + i + 3) * ND + c];
    }
    for (; i < se; i++) a0 += g_x[(size_t)(base + i) * ND + c];
    (which ? g_te : g_he)[bb * ND + c] = (a0 + a1) + (a2 + a3);
}

// ---------------- final MLP ----------------
__global__ void k_mlp(const int* __restrict__ rel, const float* __restrict__ kge,
                      const float* __restrict__ W1, const float* __restrict__ b1,
                      const float* __restrict__ W2, const float* __restrict__ b2,
                      float* __restrict__ out) {
    int b = blockIdx.x;
    int j = threadIdx.x;
    __shared__ float zin[2 * ND + HC];
    for (int k = j; k < ND; k += 64) zin[k] = g_he[b * ND + k];
    for (int k = j; k < ND; k += 64) zin[ND + k] = g_te[b * ND + k];
    int r = rel[b];
    zin[2 * ND + j] = kge[r * HC + j];
    __syncthreads();
    float z = b1[j];
    for (int k = 0; k < 2 * ND + HC; k++) z += zin[k] * W1[k * 64 + j];
    z = fmaxf(z, 0.f);
    __shared__ float zs[64];
    zs[j] = z * W2[j];
    __syncthreads();
    if (j < 32) {
        float v = zs[j] + zs[j + 32];
#pragma unroll
        for (int o = 16; o; o >>= 1) v += __shfl_xor_sync(0xffffffffu, v, o);
        if (j == 0) out[b] = v + b2[0];
    }
}

// ---------------- launcher ----------------
extern "C" void kernel_launch(void* const* d_in, const int* in_sizes, int n_in,
                              void* d_out, int out_size) {
    const float* head_x    = (const float*)d_in[0];
    const int*   head_ei   = (const int*)d_in[1];
    const int*   head_b    = (const int*)d_in[2];
    const float* tail_x    = (const float*)d_in[3];
    const int*   tail_ei   = (const int*)d_in[4];
    const int*   tail_b    = (const int*)d_in[5];
    const int*   rel       = (const int*)d_in[6];
    const float* Ws        = (const float*)d_in[7];
    const float* att_src   = (const float*)d_in[8];
    const float* att_dst   = (const float*)d_in[9];
    const float* biases    = (const float*)d_in[10];
    const float* kge       = (const float*)d_in[11];
    const float* W1        = (const float*)d_in[12];
    const float* b1        = (const float*)d_in[13];
    const float* W2        = (const float*)d_in[14];
    const float* b2        = (const float*)d_in[15];
    float*       out       = (float*)d_out;

    static cudaStream_t s2 = nullptr;
    static cudaEvent_t evF = nullptr, evJ = nullptr;
    if (!s2) {
        cudaStreamCreateWithFlags(&s2, cudaStreamNonBlocking);
        cudaEventCreateWithFlags(&evF, cudaEventDisableTiming);
        cudaEventCreateWithFlags(&evJ, cudaEventDisableTiming);
    }

    cudaFuncSetAttribute(k_gemm, cudaFuncAttributeMaxDynamicSharedMemorySize, GSMEM);

    const int TB = 256;
    __half* wh0;
    cudaGetSymbolAddress((void**)&wh0, g_wh);

    // fork: CSR build on s2, concurrent with split + GEMM0
    cudaEventRecord(evF, 0);
    cudaStreamWaitEvent(s2, evF, 0);
    k_init_counts<<<(NN2 + TB - 1) / TB, TB, 0, s2>>>();
    k_count<<<(2 * NE + TB - 1) / TB, TB, 0, s2>>>(head_ei, tail_ei);
    k_assign<<<(NN2 + TB - 1) / TB, TB, 0, s2>>>();
    k_scatter<<<(2 * NE + TB - 1) / TB, TB, 0, s2>>>(head_ei, tail_ei);
    k_selfloops<<<(NN2 + TB - 1) / TB, TB, 0, s2>>>();
    cudaEventRecord(evJ, s2);

    k_split_w<<<(3 * ND * ND + TB - 1) / TB, TB>>>(Ws);
    k_split_x<<<1184, 256>>>(head_x, tail_x);

    for (int l = 0; l < 3; l++) {
        k_gemm<<<dim3(2, (NN2 + 127) / 128), 256, GSMEM>>>(
            wh0 + (size_t)l * ND * ND, att_src + l * ND, att_dst + l * ND);
        if (l == 0) cudaStreamWaitEvent(0, evJ, 0);
        k_agg<<<NN2 / 2, 256>>>(biases + l * ND, l == 2);
    }
    k_pool<<<2 * NB, ND>>>(head_b, tail_b);
    k_mlp<<<NB, 64>>>(rel, kge, W1, b1, W2, b2, out);
}

// round 16
// speedup vs baseline: 1.5412x; 1.2355x over previous
#include <cuda_runtime.h>
#include <cuda_fp16.h>
#include <stdint.h>
#include <math.h>

#define NN 50000
#define NN2 (2 * NN)
#define NE 800000
#define ET2 (2 * (NN + NE))
#define NB 512
#define ND 256
#define NH 4
#define HC 64

// ---------------- static device scratch ----------------
__device__ float g_x[(size_t)NN2 * ND];        // final-layer activations (pooling)
__device__ __half g_xh[(size_t)NN2 * ND];      // GEMM A input (fp16)
__device__ __half g_wh[3 * ND * ND];           // weights fp16, transposed [l][n][k]
__device__ __half g_hf[(size_t)NN2 * ND];      // h gather plane (fp16)
__device__ float g_asrc[NN2 * NH];
__device__ float g_adst[NN2 * NH];
__device__ int   g_counts[NN2];
__device__ int   g_off[NN2];
__device__ int   g_cur[NN2];
__device__ int   g_srcs[ET2];
__device__ int   g_total;
__device__ float g_he[NB * ND];
__device__ float g_te[NB * ND];

// ---------------- input conversion ----------------
__global__ void k_split_x(const float* __restrict__ xh, const float* __restrict__ xt) {
    const int n4 = NN2 * ND / 4;
    const int h4 = NN * ND / 4;
    int i = blockIdx.x * blockDim.x + threadIdx.x;
    int stride = gridDim.x * blockDim.x;
    for (; i < n4; i += stride) {
        float4 v = (i < h4) ? ((const float4*)xh)[i] : ((const float4*)xt)[i - h4];
        __half2 a = __floats2half2_rn(v.x, v.y);
        __half2 b = __floats2half2_rn(v.z, v.w);
        uint2 p;
        p.x = *(unsigned*)&a;
        p.y = *(unsigned*)&b;
        ((uint2*)g_xh)[i] = p;
    }
}

__global__ void k_split_w(const float* __restrict__ Ws) {
    int i = blockIdx.x * blockDim.x + threadIdx.x;
    if (i >= 3 * ND * ND) return;
    int l = i / (ND * ND);
    int r = i % (ND * ND);
    int n = r / ND;
    int k = r % ND;
    g_wh[i] = __float2half_rn(Ws[l * ND * ND + k * ND + n]);
}

// ---------------- merged CSR construction ----------------
__global__ void k_init_counts() {
    int i = blockIdx.x * blockDim.x + threadIdx.x;
    if (i < NN2) g_counts[i] = 1;
    if (i == 0) g_total = 0;
}

__global__ void k_count(const int* __restrict__ eh, const int* __restrict__ et) {
    int e = blockIdx.x * blockDim.x + threadIdx.x;
    if (e >= 2 * NE) return;
    int d = (e < NE) ? eh[NE + e] : (et[NE + (e - NE)] + NN);
    atomicAdd(&g_counts[d], 1);
}

__global__ void k_assign() {
    int i = blockIdx.x * blockDim.x + threadIdx.x;
    int lane = threadIdx.x & 31;
    int v = (i < NN2) ? g_counts[i] : 0;
    int inc = v;
#pragma unroll
    for (int o = 1; o < 32; o <<= 1) {
        int t = __shfl_up_sync(0xffffffffu, inc, o);
        if (lane >= o) inc += t;
    }
    int wtot = __shfl_sync(0xffffffffu, inc, 31);
    int base = 0;
    if (lane == 31) base = atomicAdd(&g_total, wtot);
    base = __shfl_sync(0xffffffffu, base, 31);
    if (i < NN2) {
        int p = base + inc - v;
        g_off[i] = p;
        g_cur[i] = p;
    }
}

__global__ void k_scatter(const int* __restrict__ eh, const int* __restrict__ et) {
    int e = blockIdx.x * blockDim.x + threadIdx.x;
    if (e >= 2 * NE) return;
    int s, d;
    if (e < NE) {
        s = eh[e];
        d = eh[NE + e];
    } else {
        s = et[e - NE] + NN;
        d = et[NE + (e - NE)] + NN;
    }
    int p = atomicAdd(&g_cur[d], 1);
    g_srcs[p] = s;
}

__global__ void k_selfloops() {
    int i = blockIdx.x * blockDim.x + threadIdx.x;
    if (i >= NN2) return;
    int p = atomicAdd(&g_cur[i], 1);
    g_srcs[p] = i;
}

// ---------------- fp16 tensor-core GEMM + fused att-score epilogue ----------------
__device__ __forceinline__ void mma16816h(float* c, const unsigned* a, const unsigned* b) {
    asm volatile(
        "mma.sync.aligned.m16n8k16.row.col.f32.f16.f16.f32 "
        "{%0,%1,%2,%3},{%4,%5,%6,%7},{%8,%9},{%0,%1,%2,%3};"
        : "+f"(c[0]), "+f"(c[1]), "+f"(c[2]), "+f"(c[3])
        : "r"(a[0]), "r"(a[1]), "r"(a[2]), "r"(a[3]), "r"(b[0]), "r"(b[1]));
}

#define LDP 40
#define ARR_B 10240
#define BUF_B 20480
#define GSMEM (2 * BUF_B)    // 40 KB

__device__ __forceinline__ void cp16(uint32_t dst, const void* src, bool pred) {
    asm volatile("cp.async.cg.shared.global [%0], [%1], 16, %2;"
                 :: "r"(dst), "l"(src), "r"(pred ? 16 : 0));
}

__global__ void __launch_bounds__(256) k_gemm(const __half* __restrict__ wh,
                                              const float* __restrict__ a_s,
                                              const float* __restrict__ a_d) {
    extern __shared__ __align__(16) unsigned char smem[];
    uint32_t smem_s = (uint32_t)__cvta_generic_to_shared(smem);
    int tid = threadIdx.x;
    int bx = blockIdx.x;
    int mBase = blockIdx.y * 128, nBase = bx * 128;
    int w = tid >> 5, lane = tid & 31;
    int wm = w >> 2, wn = w & 3;
    int g = lane >> 2, thr = lane & 3;
    float c[4][4][4];
#pragma unroll
    for (int a = 0; a < 4; a++)
#pragma unroll
        for (int b = 0; b < 4; b++)
#pragma unroll
            for (int d = 0; d < 4; d++) c[a][b][d] = 0.f;

    int i0 = tid, i1 = tid + 256;
    int r0c = i0 >> 2, ch0 = (i0 & 3) * 8;
    int r1c = i1 >> 2, ch1 = (i1 & 3) * 8;
    bool p0 = (mBase + r0c) < NN2, p1 = (mBase + r1c) < NN2;
    size_t aof0 = (size_t)(mBase + r0c) * ND + ch0;
    size_t aof1 = (size_t)(mBase + r1c) * ND + ch1;
    size_t bof0 = (size_t)(nBase + r0c) * ND + ch0;
    size_t bof1 = (size_t)(nBase + r1c) * ND + ch1;
    uint32_t d00 = smem_s + r0c * 80 + ch0 * 2;
    uint32_t d01 = smem_s + r1c * 80 + ch1 * 2;

    auto issue = [&](int t, int buf) {
        int k0 = t * 32;
        uint32_t bb = (uint32_t)buf * BUF_B;
        cp16(d00 + bb,         g_xh + aof0 + k0, p0);
        cp16(d01 + bb,         g_xh + aof1 + k0, p1);
        cp16(d00 + bb + ARR_B, wh + bof0 + k0, true);
        cp16(d01 + bb + ARR_B, wh + bof1 + k0, true);
        asm volatile("cp.async.commit_group;");
    };

    issue(0, 0);
    for (int t = 0; t < 8; t++) {
        if (t < 7) {
            issue(t + 1, (t + 1) & 1);
            asm volatile("cp.async.wait_group 1;");
        } else {
            asm volatile("cp.async.wait_group 0;");
        }
        __syncthreads();

        const __half* Ah = (const __half*)(smem + (t & 1) * BUF_B);
        const __half* Bh = Ah + 5120;

#pragma unroll
        for (int kk = 0; kk < 32; kk += 16) {
            unsigned bf[4][2];
#pragma unroll
            for (int ni = 0; ni < 4; ni++) {
                int nr = wn * 32 + ni * 8 + g;
                bf[ni][0] = *(const unsigned*)&Bh[nr * LDP + kk + thr * 2];
                bf[ni][1] = *(const unsigned*)&Bh[nr * LDP + kk + thr * 2 + 8];
            }
#pragma unroll
            for (int mi = 0; mi < 4; mi++) {
                int r0 = wm * 64 + mi * 16 + g;
                unsigned af[4];
                af[0] = *(const unsigned*)&Ah[r0 * LDP + kk + thr * 2];
                af[1] = *(const unsigned*)&Ah[(r0 + 8) * LDP + kk + thr * 2];
                af[2] = *(const unsigned*)&Ah[r0 * LDP + kk + thr * 2 + 8];
                af[3] = *(const unsigned*)&Ah[(r0 + 8) * LDP + kk + thr * 2 + 8];
#pragma unroll
                for (int ni = 0; ni < 4; ni++) mma16816h(c[mi][ni], af, bf[ni]);
            }
        }
        __syncthreads();
    }

    // ---- store h (fp16 gather plane) ----
#pragma unroll
    for (int mi = 0; mi < 4; mi++) {
        int row0 = mBase + wm * 64 + mi * 16 + g;
#pragma unroll
        for (int ni = 0; ni < 4; ni++) {
            int col = nBase + wn * 32 + ni * 8 + thr * 2;
            if (row0 < NN2)
                *(__half2*)&g_hf[(size_t)row0 * ND + col] =
                    __floats2half2_rn(c[mi][ni][0], c[mi][ni][1]);
            if (row0 + 8 < NN2)
                *(__half2*)&g_hf[(size_t)(row0 + 8) * ND + col] =
                    __floats2half2_rn(c[mi][ni][2], c[mi][ni][3]);
        }
    }

    // ---- fused attention-score epilogue (fp32) ----
    float2 asv[4], adv[4];
#pragma unroll
    for (int ni = 0; ni < 4; ni++) {
        int col = nBase + wn * 32 + ni * 8 + thr * 2;
        asv[ni] = *(const float2*)&a_s[col];
        adv[ni] = *(const float2*)&a_d[col];
    }
    float ps[4][2], pd[4][2];
#pragma unroll
    for (int mi = 0; mi < 4; mi++) {
        ps[mi][0] = ps[mi][1] = pd[mi][0] = pd[mi][1] = 0.f;
#pragma unroll
        for (int ni = 0; ni < 4; ni++) {
            ps[mi][0] += c[mi][ni][0] * asv[ni].x + c[mi][ni][1] * asv[ni].y;
            ps[mi][1] += c[mi][ni][2] * asv[ni].x + c[mi][ni][3] * asv[ni].y;
            pd[mi][0] += c[mi][ni][0] * adv[ni].x + c[mi][ni][1] * adv[ni].y;
            pd[mi][1] += c[mi][ni][2] * adv[ni].x + c[mi][ni][3] * adv[ni].y;
        }
    }
#pragma unroll
    for (int off = 1; off < 4; off <<= 1) {
#pragma unroll
        for (int mi = 0; mi < 4; mi++) {
#pragma unroll
            for (int j = 0; j < 2; j++) {
                ps[mi][j] += __shfl_xor_sync(0xffffffffu, ps[mi][j], off);
                pd[mi][j] += __shfl_xor_sync(0xffffffffu, pd[mi][j], off);
            }
        }
    }
    float2* arr = (float2*)smem;
    if (thr == 0) {
#pragma unroll
        for (int mi = 0; mi < 4; mi++) {
#pragma unroll
            for (int j = 0; j < 2; j++) {
                int row = wm * 64 + mi * 16 + g + j * 8;
                arr[row * 4 + wn] = make_float2(ps[mi][j], pd[mi][j]);
            }
        }
    }
    __syncthreads();
    if (tid < 128) {
        int rg = mBase + tid;
        if (rg < NN2) {
            float2 q0 = arr[tid * 4 + 0], q1 = arr[tid * 4 + 1];
            float2 q2 = arr[tid * 4 + 2], q3 = arr[tid * 4 + 3];
            int hb = bx * 2;
            g_asrc[rg * 4 + hb]     = q0.x + q1.x;
            g_asrc[rg * 4 + hb + 1] = q2.x + q3.x;
            g_adst[rg * 4 + hb]     = q0.y + q1.y;
            g_adst[rg * 4 + hb + 1] = q2.y + q3.y;
        }
    }
}

// ---------------- aggregation: ONE WARP PER NODE, lane owns 8 cols ----------------
__global__ void __launch_bounds__(256) k_agg(const float* __restrict__ bias, int last) {
    int warp = threadIdx.x >> 5;
    int lane = threadIdx.x & 31;
    int node = blockIdx.x * 8 + warp;
    if (node >= NN2) return;
    int beg = g_off[node];
    int cnt_all = g_counts[node];
    float4 adn = *(const float4*)&g_adst[node * 4];
    int head = lane >> 3;         // 0..3: which head my 8 columns belong to
    int col = lane * 8;
    const __half* hf = g_hf + col;

    float acc[8] = {0.f, 0.f, 0.f, 0.f, 0.f, 0.f, 0.f, 0.f};
    float4 den4 = make_float4(0.f, 0.f, 0.f, 0.f);

    // compute all 4 head-eas for edge with source s
    auto edge_ea = [&](int s) -> float4 {
        float4 as = *(const float4*)&g_asrc[s * 4];
        float a;
        float4 e;
        a = as.x + adn.x; a = a > 0.f ? a : 0.2f * a; e.x = __expf(a);
        a = as.y + adn.y; a = a > 0.f ? a : 0.2f * a; e.y = __expf(a);
        a = as.z + adn.z; a = a > 0.f ? a : 0.2f * a; e.z = __expf(a);
        a = as.w + adn.w; a = a > 0.f ? a : 0.2f * a; e.w = __expf(a);
        return e;
    };
    auto gather1 = [&](float4 e, int s, int j) {
        float ex = __shfl_sync(0xffffffffu, e.x, j);
        float ey = __shfl_sync(0xffffffffu, e.y, j);
        float ez = __shfl_sync(0xffffffffu, e.z, j);
        float ew = __shfl_sync(0xffffffffu, e.w, j);
        int sj = __shfl_sync(0xffffffffu, s, j);
        float em = head < 2 ? (head == 0 ? ex : ey) : (head == 2 ? ez : ew);
        uint4 hv = *(const uint4*)(hf + (size_t)sj * ND);
        float2 f0 = __half22float2(*(__half2*)&hv.x);
        float2 f1 = __half22float2(*(__half2*)&hv.y);
        float2 f2 = __half22float2(*(__half2*)&hv.z);
        float2 f3 = __half22float2(*(__half2*)&hv.w);
        acc[0] += em * f0.x; acc[1] += em * f0.y;
        acc[2] += em * f1.x; acc[3] += em * f1.y;
        acc[4] += em * f2.x; acc[5] += em * f2.y;
        acc[6] += em * f3.x; acc[7] += em * f3.y;
    };

    for (int base = beg; base < beg + cnt_all; base += 32) {
        int i = base + lane;
        bool ok = i < beg + cnt_all;
        int s = ok ? g_srcs[i] : 0;
        float4 e = ok ? edge_ea(s) : make_float4(0.f, 0.f, 0.f, 0.f);
        den4.x += e.x; den4.y += e.y; den4.z += e.z; den4.w += e.w;
        int cnt = min(32, beg + cnt_all - base);
        for (int j = 0; j < cnt; j++) gather1(e, s, j);
    }

    // warp-reduce denominators (all 4 heads)
#pragma unroll
    for (int o = 16; o; o >>= 1) {
        den4.x += __shfl_xor_sync(0xffffffffu, den4.x, o);
        den4.y += __shfl_xor_sync(0xffffffffu, den4.y, o);
        den4.z += __shfl_xor_sync(0xffffffffu, den4.z, o);
        den4.w += __shfl_xor_sync(0xffffffffu, den4.w, o);
    }
    float dmy = head < 2 ? (head == 0 ? den4.x : den4.y) : (head == 2 ? den4.z : den4.w);
    float inv = 1.0f / dmy;

    float4 b0 = *(const float4*)&bias[col];
    float4 b1 = *(const float4*)&bias[col + 4];
    float v[8];
    v[0] = acc[0] * inv + b0.x; v[1] = acc[1] * inv + b0.y;
    v[2] = acc[2] * inv + b0.z; v[3] = acc[3] * inv + b0.w;
    v[4] = acc[4] * inv + b1.x; v[5] = acc[5] * inv + b1.y;
    v[6] = acc[6] * inv + b1.z; v[7] = acc[7] * inv + b1.w;
#pragma unroll
    for (int k = 0; k < 8; k++) v[k] = v[k] > 0.f ? v[k] : expm1f(v[k]);

    size_t o0 = (size_t)node * ND + col;
    uint4 hx;
    __half2 t0 = __floats2half2_rn(v[0], v[1]);
    __half2 t1 = __floats2half2_rn(v[2], v[3]);
    __half2 t2 = __floats2half2_rn(v[4], v[5]);
    __half2 t3 = __floats2half2_rn(v[6], v[7]);
    hx.x = *(unsigned*)&t0; hx.y = *(unsigned*)&t1;
    hx.z = *(unsigned*)&t2; hx.w = *(unsigned*)&t3;
    *(uint4*)(g_xh + o0) = hx;
    if (last) {
        *(float4*)(g_x + o0)     = make_float4(v[0], v[1], v[2], v[3]);
        *(float4*)(g_x + o0 + 4) = make_float4(v[4], v[5], v[6], v[7]);
    }
}

// ---------------- pooling (4-way unrolled) ----------------
__global__ void k_pool(const int* __restrict__ hb, const int* __restrict__ tb) {
    __shared__ int sb, se;
    int b = blockIdx.x;
    int which = b >= NB;
    int bb = which ? b - NB : b;
    const int* batch = which ? tb : hb;
    if (threadIdx.x == 0) {
        int lo = 0, hi = NN;
        while (lo < hi) { int mid = (lo + hi) >> 1; if (batch[mid] < bb) lo = mid + 1; else hi = mid; }
        sb = lo;
        lo = 0; hi = NN;
        while (lo < hi) { int mid = (lo + hi) >> 1; if (batch[mid] < bb + 1) lo = mid + 1; else hi = mid; }
        se = lo;
    }
    __syncthreads();
    int c = threadIdx.x;
    int base = which ? NN : 0;
    float a0 = 0.f, a1 = 0.f, a2 = 0.f, a3 = 0.f;
    int i = sb;
    for (; i + 4 <= se; i += 4) {
        a0 += g_x[(size_t)(base + i) * ND + c];
        a1 += g_x[(size_t)(base + i + 1) * ND + c];
        a2 += g_x[(size_t)(base + i + 2) * ND + c];
        a3 += g_x[(size_t)(base + i + 3) * ND + c];
    }
    for (; i < se; i++) a0 += g_x[(size_t)(base + i) * ND + c];
    (which ? g_te : g_he)[bb * ND + c] = (a0 + a1) + (a2 + a3);
}

// ---------------- final MLP ----------------
__global__ void k_mlp(const int* __restrict__ rel, const float* __restrict__ kge,
                      const float* __restrict__ W1, const float* __restrict__ b1,
                      const float* __restrict__ W2, const float* __restrict__ b2,
                      float* __restrict__ out) {
    int b = blockIdx.x;
    int j = threadIdx.x;
    __shared__ float zin[2 * ND + HC];
    for (int k = j; k < ND; k += 64) zin[k] = g_he[b * ND + k];
    for (int k = j; k < ND; k += 64) zin[ND + k] = g_te[b * ND + k];
    int r = rel[b];
    zin[2 * ND + j] = kge[r * HC + j];
    __syncthreads();
    float z = b1[j];
    for (int k = 0; k < 2 * ND + HC; k++) z += zin[k] * W1[k * 64 + j];
    z = fmaxf(z, 0.f);
    __shared__ float zs[64];
    zs[j] = z * W2[j];
    __syncthreads();
    if (j < 32) {
        float v = zs[j] + zs[j + 32];
#pragma unroll
        for (int o = 16; o; o >>= 1) v += __shfl_xor_sync(0xffffffffu, v, o);
        if (j == 0) out[b] = v + b2[0];
    }
}

// ---------------- launcher ----------------
extern "C" void kernel_launch(void* const* d_in, const int* in_sizes, int n_in,
                              void* d_out, int out_size) {
    const float* head_x    = (const float*)d_in[0];
    const int*   head_ei   = (const int*)d_in[1];
    const int*   head_b    = (const int*)d_in[2];
    const float* tail_x    = (const float*)d_in[3];
    const int*   tail_ei   = (const int*)d_in[4];
    const int*   tail_b    = (const int*)d_in[5];
    const int*   rel       = (const int*)d_in[6];
    const float* Ws        = (const float*)d_in[7];
    const float* att_src   = (const float*)d_in[8];
    const float* att_dst   = (const float*)d_in[9];
    const float* biases    = (const float*)d_in[10];
    const float* kge       = (const float*)d_in[11];
    const float* W1        = (const float*)d_in[12];
    const float* b1        = (const float*)d_in[13];
    const float* W2        = (const float*)d_in[14];
    const float* b2        = (const float*)d_in[15];
    float*       out       = (float*)d_out;

    static cudaStream_t s2 = nullptr;
    static cudaEvent_t evF = nullptr, evJ = nullptr;
    if (!s2) {
        cudaStreamCreateWithFlags(&s2, cudaStreamNonBlocking);
        cudaEventCreateWithFlags(&evF, cudaEventDisableTiming);
        cudaEventCreateWithFlags(&evJ, cudaEventDisableTiming);
    }

    cudaFuncSetAttribute(k_gemm, cudaFuncAttributeMaxDynamicSharedMemorySize, GSMEM);

    const int TB = 256;
    __half* wh0;
    cudaGetSymbolAddress((void**)&wh0, g_wh);

    // fork: CSR build on s2, concurrent with split + GEMM0
    cudaEventRecord(evF, 0);
    cudaStreamWaitEvent(s2, evF, 0);
    k_init_counts<<<(NN2 + TB - 1) / TB, TB, 0, s2>>>();
    k_count<<<(2 * NE + TB - 1) / TB, TB, 0, s2>>>(head_ei, tail_ei);
    k_assign<<<(NN2 + TB - 1) / TB, TB, 0, s2>>>();
    k_scatter<<<(2 * NE + TB - 1) / TB, TB, 0, s2>>>(head_ei, tail_ei);
    k_selfloops<<<(NN2 + TB - 1) / TB, TB, 0, s2>>>();
    cudaEventRecord(evJ, s2);

    k_split_w<<<(3 * ND * ND + TB - 1) / TB, TB>>>(Ws);
    k_split_x<<<1184, 256>>>(head_x, tail_x);

    for (int l = 0; l < 3; l++) {
        k_gemm<<<dim3(2, (NN2 + 127) / 128), 256, GSMEM>>>(
            wh0 + (size_t)l * ND * ND, att_src + l * ND, att_dst + l * ND);
        if (l == 0) cudaStreamWaitEvent(0, evJ, 0);
        k_agg<<<NN2 / 8, 256>>>(biases + l * ND, l == 2);
    }
    k_pool<<<2 * NB, ND>>>(head_b, tail_b);
    k_mlp<<<NB, 64>>>(rel, kge, W1, b1, W2, b2, out);
}